// round 13
// baseline (speedup 1.0000x reference)
#include <cuda_runtime.h>
#include <cstdint>
#include <cstddef>

#define BB 4
#define SS 2048
#define DM 1024
#define NH 16
#define DK 64

// Scratch (allocation-free rule: __device__ globals)
__device__ float g_Pq[BB * SS * DM];
__device__ float g_Pk[BB * SS * DM];
__device__ float g_Pv[BB * SS * DM];
__device__ float g_ctxT[BB * SS * DM];
__device__ float g_fc[BB * SS * DM];
__device__ float g_attn_fallback[(size_t)BB * NH * SS * SS];

__device__ __forceinline__ uint32_t f2tf(float x) {
  uint32_t u;
  asm("cvt.rna.tf32.f32 %0, %1;" : "=r"(u) : "f"(x));
  return u;
}
__device__ __forceinline__ uint32_t tfr(uint32_t x) {  // RNA-round raw fp32 bits
  uint32_t u;
  asm("cvt.rna.tf32.f32 %0, %1;" : "=r"(u) : "f"(__uint_as_float(x)));
  return u;
}
__device__ __forceinline__ uint32_t su(const void* p) {
  return (uint32_t)__cvta_generic_to_shared(p);
}
__device__ __forceinline__ void cpa16(uint32_t s, const void* g) {
  asm volatile("cp.async.cg.shared.global [%0], [%1], 16;\n" ::"r"(s), "l"(g));
}
__device__ __forceinline__ void cpcommit() {
  asm volatile("cp.async.commit_group;\n");
}
template <int N>
__device__ __forceinline__ void cpwait() {
  asm volatile("cp.async.wait_group %0;\n" ::"n"(N));
}
__device__ __forceinline__ void ldsm4(uint32_t& r0, uint32_t& r1, uint32_t& r2,
                                      uint32_t& r3, uint32_t a) {
  asm volatile(
      "ldmatrix.sync.aligned.m8n8.x4.shared.b16 {%0,%1,%2,%3},[%4];\n"
      : "=r"(r0), "=r"(r1), "=r"(r2), "=r"(r3)
      : "r"(a));
}
__device__ __forceinline__ void mma_tf32(float* c, uint32_t a0, uint32_t a1,
                                         uint32_t a2, uint32_t a3, uint32_t b0,
                                         uint32_t b1) {
  asm volatile(
      "mma.sync.aligned.m16n8k8.row.col.f32.tf32.tf32.f32 "
      "{%0,%1,%2,%3},{%4,%5,%6,%7},{%8,%9},{%0,%1,%2,%3};\n"
      : "+f"(c[0]), "+f"(c[1]), "+f"(c[2]), "+f"(c[3])
      : "r"(a0), "r"(a1), "r"(a2), "r"(a3), "r"(b0), "r"(b1));
}

// ---------------------------------------------------------------------------
// tf32 GEMM core (NT): C[M,N] = A[M,K] * W[N,K]^T. 128x128 tile, BK=32,
// 8 warps, warp tile 32x64. 2-stage cp.async pipeline: one sync per K-iter,
// prefetch for kt+1 issued BEFORE the mma block (mma covers load latency).
// smem holds raw fp32; cvt.rna applied after LDS (same RNA values as R5 ->
// bit-identical products). Fragment scheme identical to proven R5 kernel.
// smem: 2 stages x (A 128x36 + B 128x36) words = 73728 B.
// ---------------------------------------------------------------------------
#define GST 36
#define GSTG (128 * GST)  // words per matrix per stage
#define GEMM_SMEM (4 * GSTG * 4)

template <bool RND>
__device__ __forceinline__ void gemm_core(const float* __restrict__ A,
                                          const float* __restrict__ Bw,
                                          float* __restrict__ C, int M, int N,
                                          int K, uint32_t* smg) {
  int tid = threadIdx.x, lane = tid & 31, wid = tid >> 5;
  int g = lane >> 2, tg = lane & 3;
  int m0 = (wid & 3) * 32, n0 = (wid >> 2) * 64;
  int bm = blockIdx.y * 128, bn = blockIdx.x * 128;

  uint32_t* As = smg;
  uint32_t* Bs = smg + 2 * GSTG;
  uint32_t sA = su(As), sB = su(Bs);

  int cm[4], ck[4];
#pragma unroll
  for (int i = 0; i < 4; i++) {
    int id = tid + i * 256;
    cm[i] = id >> 3;
    ck[i] = (id & 7) << 2;
  }

  float c[2][8][4];
#pragma unroll
  for (int mt = 0; mt < 2; mt++)
#pragma unroll
    for (int nt = 0; nt < 8; nt++)
#pragma unroll
      for (int j = 0; j < 4; j++) c[mt][nt][j] = 0.f;

  // prologue: stage 0
#pragma unroll
  for (int i = 0; i < 4; i++) {
    cpa16(sA + (cm[i] * GST + ck[i]) * 4, &A[(size_t)(bm + cm[i]) * K + ck[i]]);
    cpa16(sB + (cm[i] * GST + ck[i]) * 4,
          &Bw[(size_t)(bn + cm[i]) * K + ck[i]]);
  }
  cpcommit();

  int NIT = K / 32;
  for (int kt = 0; kt < NIT; kt++) {
    int st = kt & 1;
    cpwait<0>();
    __syncthreads();  // stage st ready; all warps done reading st^1

    if (kt + 1 < NIT) {
      int k0 = (kt + 1) * 32;
#pragma unroll
      for (int i = 0; i < 4; i++) {
        cpa16(sA + ((st ^ 1) * GSTG + cm[i] * GST + ck[i]) * 4,
              &A[(size_t)(bm + cm[i]) * K + k0 + ck[i]]);
        cpa16(sB + ((st ^ 1) * GSTG + cm[i] * GST + ck[i]) * 4,
              &Bw[(size_t)(bn + cm[i]) * K + k0 + ck[i]]);
      }
      cpcommit();
    }

    const uint32_t* Ast = As + st * GSTG;
    const uint32_t* Bst = Bs + st * GSTG;
#pragma unroll
    for (int kk = 0; kk < 4; kk++) {
      int k = kk * 8;
      uint32_t a[2][4];
#pragma unroll
      for (int mt = 0; mt < 2; mt++) {
        int mm = m0 + mt * 16 + g;
        a[mt][0] = tfr(Ast[mm * GST + k + tg]);
        a[mt][1] = tfr(Ast[(mm + 8) * GST + k + tg]);
        a[mt][2] = tfr(Ast[mm * GST + k + tg + 4]);
        a[mt][3] = tfr(Ast[(mm + 8) * GST + k + tg + 4]);
      }
#pragma unroll
      for (int nt = 0; nt < 8; nt++) {
        int nn = n0 + nt * 8 + g;
        uint32_t b0 = tfr(Bst[nn * GST + k + tg]);
        uint32_t b1 = tfr(Bst[nn * GST + k + tg + 4]);
        mma_tf32(c[0][nt], a[0][0], a[0][1], a[0][2], a[0][3], b0, b1);
        mma_tf32(c[1][nt], a[1][0], a[1][1], a[1][2], a[1][3], b0, b1);
      }
    }
  }

#pragma unroll
  for (int mt = 0; mt < 2; mt++)
#pragma unroll
    for (int nt = 0; nt < 8; nt++) {
      int row0 = bm + m0 + mt * 16 + g;
      int col = bn + n0 + nt * 8 + 2 * tg;
      float v0 = c[mt][nt][0], v1 = c[mt][nt][1];
      float v2 = c[mt][nt][2], v3 = c[mt][nt][3];
      if (RND) {
        v0 = __uint_as_float(f2tf(v0));
        v1 = __uint_as_float(f2tf(v1));
        v2 = __uint_as_float(f2tf(v2));
        v3 = __uint_as_float(f2tf(v3));
      }
      *(float2*)&C[(size_t)row0 * N + col] = make_float2(v0, v1);
      *(float2*)&C[(size_t)(row0 + 8) * N + col] = make_float2(v2, v3);
    }
}

// Fused QKV projections: gridDim.z selects (input, weight, output).
// 192 blocks in one launch instead of 3 half-empty 64-block waves.
__global__ __launch_bounds__(256) void gemm_qkv(
    const float* __restrict__ q, const float* __restrict__ k,
    const float* __restrict__ v, const float* __restrict__ wq,
    const float* __restrict__ wk, const float* __restrict__ wv,
    float* __restrict__ Pq, float* __restrict__ Pk, float* __restrict__ Pv) {
  extern __shared__ uint32_t smg[];
  const float* A = (blockIdx.z == 0) ? q : (blockIdx.z == 1) ? k : v;
  const float* W = (blockIdx.z == 0) ? wq : (blockIdx.z == 1) ? wk : wv;
  float* C = (blockIdx.z == 0) ? Pq : (blockIdx.z == 1) ? Pk : Pv;
  gemm_core<true>(A, W, C, BB * SS, DM, DM, smg);
}

__global__ __launch_bounds__(256) void gemm_fc(const float* __restrict__ A,
                                               const float* __restrict__ W,
                                               float* __restrict__ C) {
  extern __shared__ uint32_t smg[];
  gemm_core<false>(A, W, C, BB * SS, DM, DM, smg);
}

// ---------------------------------------------------------------------------
// Attention, two-pass normalization, 32-row warp tiles (proven R11 kernel).
// ---------------------------------------------------------------------------
#define AST 68
#define VST 72
#define QS_W 0
#define KS_W 8704
#define KS_STG 4352
#define VS_W 17408
#define VS_STG 4608
#define ATTN_SMEM (26624 * 4)

__global__ __launch_bounds__(128, 2) void attn_kernel(
    const float* __restrict__ Pq, const float* __restrict__ Pk,
    const float* __restrict__ Pv, float* __restrict__ attn,
    float* __restrict__ ctxT) {
  extern __shared__ float smf[];

  int tid = threadIdx.x, lane = tid & 31, wid = tid >> 5;
  int sub = lane >> 3, l7 = lane & 7;
  int g = lane >> 2, tg = lane & 3;
  int m0 = wid * 32;    // warp's 32 Q-rows (block-local)
  int qt = blockIdx.x;  // 0..15 (128-row Q tiles)
  int bh = blockIdx.y;
  int b = bh >> 4, h = bh & 15;

  const float* Qb = Pq + (size_t)b * SS * DM + (size_t)h * SS * DK;
  const float* Kb = Pk + (size_t)b * SS * DM + (size_t)h * SS * DK;
  const float* Vb = Pv + (size_t)b * SS * DM + (size_t)h * SS * DK;
  float* attn_b = attn + ((size_t)bh * SS + (size_t)qt * 128) * SS;

  uint32_t sbase = su(smf);

  uint32_t qOff0 =
      sbase + (QS_W + (m0 + (sub & 1) * 8 + l7) * AST + (sub >> 1) * 4) * 4;
  uint32_t qOff1 = qOff0 + 16 * AST * 4;
  uint32_t kLane = (((sub >> 1) * 8 + l7) * AST + (sub & 1) * 4) * 4;

  int qrow[16], qcol[16];
#pragma unroll
  for (int i = 0; i < 16; i++) {
    int cc = tid + i * 128;
    qrow[i] = cc >> 4;
    qcol[i] = (cc & 15) << 2;
  }
  int crow[8], ccol[8];
#pragma unroll
  for (int i = 0; i < 8; i++) {
    int cc = tid + i * 128;
    crow[i] = cc >> 4;
    ccol[i] = (cc & 15) << 2;
  }

  // prologue: Q + K0 + V0 (one group)
#pragma unroll
  for (int i = 0; i < 16; i++)
    cpa16(sbase + (QS_W + qrow[i] * AST + qcol[i]) * 4,
          Qb + (size_t)(qt * 128 + qrow[i]) * DK + qcol[i]);
#pragma unroll
  for (int i = 0; i < 8; i++) {
    cpa16(sbase + (KS_W + crow[i] * AST + ccol[i]) * 4,
          Kb + (size_t)crow[i] * DK + ccol[i]);
    cpa16(sbase + (VS_W + crow[i] * VST + ccol[i]) * 4,
          Vb + (size_t)crow[i] * DK + ccol[i]);
  }
  cpcommit();

  float o[2][8][4];
#pragma unroll
  for (int mt = 0; mt < 2; mt++)
#pragma unroll
    for (int nt = 0; nt < 8; nt++)
#pragma unroll
      for (int j = 0; j < 4; j++) o[mt][nt][j] = 0.f;
  float racc[2][2] = {{0.f, 0.f}, {0.f, 0.f}};

  const int NT = SS / 64;

  // ================= Pass A: rowsums + PV (no attn write) =================
  for (int kt = 0; kt < NT; kt++) {
    int st = kt & 1;
    cpwait<0>();
    __syncthreads();

    if (kt + 1 < NT) {
#pragma unroll
      for (int i = 0; i < 8; i++) {
        cpa16(sbase + (KS_W + (st ^ 1) * KS_STG + crow[i] * AST + ccol[i]) * 4,
              Kb + (size_t)((kt + 1) * 64 + crow[i]) * DK + ccol[i]);
        cpa16(sbase + (VS_W + (st ^ 1) * VS_STG + crow[i] * VST + ccol[i]) * 4,
              Vb + (size_t)((kt + 1) * 64 + crow[i]) * DK + ccol[i]);
      }
      cpcommit();
    }

    float s[2][8][4];
#pragma unroll
    for (int mt = 0; mt < 2; mt++)
#pragma unroll
      for (int nt = 0; nt < 8; nt++)
#pragma unroll
        for (int j = 0; j < 4; j++) s[mt][nt][j] = 0.f;
    uint32_t kBase = sbase + (KS_W + st * KS_STG) * 4 + kLane;
#pragma unroll
    for (int kk = 0; kk < 8; kk++) {
      uint32_t qa0[4], qa1[4];
      ldsm4(qa0[0], qa0[1], qa0[2], qa0[3], qOff0 + kk * 32);
      ldsm4(qa1[0], qa1[1], qa1[2], qa1[3], qOff1 + kk * 32);
#pragma unroll
      for (int p = 0; p < 4; p++) {
        uint32_t kb[4];
        ldsm4(kb[0], kb[1], kb[2], kb[3], kBase + p * 16 * AST * 4 + kk * 32);
        mma_tf32(s[0][2 * p], qa0[0], qa0[1], qa0[2], qa0[3], kb[0], kb[1]);
        mma_tf32(s[0][2 * p + 1], qa0[0], qa0[1], qa0[2], qa0[3], kb[2], kb[3]);
        mma_tf32(s[1][2 * p], qa1[0], qa1[1], qa1[2], qa1[3], kb[0], kb[1]);
        mma_tf32(s[1][2 * p + 1], qa1[0], qa1[1], qa1[2], qa1[3], kb[2], kb[3]);
      }
    }

    // fused exp + PV per k-step kk
    int vsBase = VS_W + st * VS_STG;
#pragma unroll
    for (int kk = 0; kk < 8; kk++) {
      uint32_t a[2][4];
#pragma unroll
      for (int mt = 0; mt < 2; mt++) {
        float e0 = __expf(s[mt][kk][0] * 0.125f);
        float e1 = __expf(s[mt][kk][1] * 0.125f);
        float e2 = __expf(s[mt][kk][2] * 0.125f);
        float e3 = __expf(s[mt][kk][3] * 0.125f);
        racc[mt][0] += e0 + e1;
        racc[mt][1] += e2 + e3;
        uint32_t t0 = f2tf(e0), t1 = f2tf(e1), t2 = f2tf(e2), t3 = f2tf(e3);
        int qlo = tg >> 1, qhi = (tg >> 1) + 2;
        uint32_t lo0 = __shfl_sync(0xffffffffu, t0, qlo, 4);
        uint32_t lo1 = __shfl_sync(0xffffffffu, t1, qlo, 4);
        uint32_t lo2 = __shfl_sync(0xffffffffu, t2, qlo, 4);
        uint32_t lo3 = __shfl_sync(0xffffffffu, t3, qlo, 4);
        uint32_t hi0 = __shfl_sync(0xffffffffu, t0, qhi, 4);
        uint32_t hi1 = __shfl_sync(0xffffffffu, t1, qhi, 4);
        uint32_t hi2 = __shfl_sync(0xffffffffu, t2, qhi, 4);
        uint32_t hi3 = __shfl_sync(0xffffffffu, t3, qhi, 4);
        a[mt][0] = (tg & 1) ? lo1 : lo0;
        a[mt][1] = (tg & 1) ? lo3 : lo2;
        a[mt][2] = (tg & 1) ? hi1 : hi0;
        a[mt][3] = (tg & 1) ? hi3 : hi2;
      }
      int kr0 = vsBase + (kk * 8 + tg) * VST;
      int kr1 = vsBase + (kk * 8 + tg + 4) * VST;
#pragma unroll
      for (int nt = 0; nt < 8; nt++) {
        uint32_t b0 = __float_as_uint(smf[kr0 + nt * 8 + g]);
        uint32_t b1 = __float_as_uint(smf[kr1 + nt * 8 + g]);
        mma_tf32(o[0][nt], a[0][0], a[0][1], a[0][2], a[0][3], b0, b1);
        mma_tf32(o[1][nt], a[1][0], a[1][1], a[1][2], a[1][3], b0, b1);
      }
    }
  }

  // quad-reduce rowsums
  float rl[2][2];
#pragma unroll
  for (int mt = 0; mt < 2; mt++)
#pragma unroll
    for (int i = 0; i < 2; i++) {
      float r = racc[mt][i];
      r += __shfl_xor_sync(0xffffffffu, r, 1);
      r += __shfl_xor_sync(0xffffffffu, r, 2);
      rl[mt][i] = 1.f / r;
    }

  // normalize ctx, write [b, s, h*64 + d]
#pragma unroll
  for (int mt = 0; mt < 2; mt++) {
    int row0 = qt * 128 + m0 + mt * 16 + g, row1 = row0 + 8;
#pragma unroll
    for (int nt = 0; nt < 8; nt++) {
      int col = h * DK + nt * 8 + 2 * tg;
      *(float2*)&g_ctxT[(size_t)b * SS * DM + (size_t)row0 * DM + col] =
          make_float2(o[mt][nt][0] * rl[mt][0], o[mt][nt][1] * rl[mt][0]);
      *(float2*)&g_ctxT[(size_t)b * SS * DM + (size_t)row1 * DM + col] =
          make_float2(o[mt][nt][2] * rl[mt][1], o[mt][nt][3] * rl[mt][1]);
    }
  }
  (void)ctxT;

  // ======= Pass B: recompute S bitwise-identically, write normalized =======
#pragma unroll
  for (int i = 0; i < 8; i++)
    cpa16(sbase + (KS_W + crow[i] * AST + ccol[i]) * 4,
          Kb + (size_t)crow[i] * DK + ccol[i]);
  cpcommit();

  for (int kt = 0; kt < NT; kt++) {
    int st = kt & 1;
    cpwait<0>();
    __syncthreads();

    if (kt + 1 < NT) {
#pragma unroll
      for (int i = 0; i < 8; i++)
        cpa16(sbase + (KS_W + (st ^ 1) * KS_STG + crow[i] * AST + ccol[i]) * 4,
              Kb + (size_t)((kt + 1) * 64 + crow[i]) * DK + ccol[i]);
      cpcommit();
    }

    float s[2][8][4];
#pragma unroll
    for (int mt = 0; mt < 2; mt++)
#pragma unroll
      for (int nt = 0; nt < 8; nt++)
#pragma unroll
        for (int j = 0; j < 4; j++) s[mt][nt][j] = 0.f;
    uint32_t kBase = sbase + (KS_W + st * KS_STG) * 4 + kLane;
#pragma unroll
    for (int kk = 0; kk < 8; kk++) {
      uint32_t qa0[4], qa1[4];
      ldsm4(qa0[0], qa0[1], qa0[2], qa0[3], qOff0 + kk * 32);
      ldsm4(qa1[0], qa1[1], qa1[2], qa1[3], qOff1 + kk * 32);
#pragma unroll
      for (int p = 0; p < 4; p++) {
        uint32_t kb[4];
        ldsm4(kb[0], kb[1], kb[2], kb[3], kBase + p * 16 * AST * 4 + kk * 32);
        mma_tf32(s[0][2 * p], qa0[0], qa0[1], qa0[2], qa0[3], kb[0], kb[1]);
        mma_tf32(s[0][2 * p + 1], qa0[0], qa0[1], qa0[2], qa0[3], kb[2], kb[3]);
        mma_tf32(s[1][2 * p], qa1[0], qa1[1], qa1[2], qa1[3], kb[0], kb[1]);
        mma_tf32(s[1][2 * p + 1], qa1[0], qa1[1], qa1[2], qa1[3], kb[2], kb[3]);
      }
    }

#pragma unroll
    for (int mt = 0; mt < 2; mt++) {
      int row0 = m0 + mt * 16 + g, row1 = row0 + 8;
#pragma unroll
      for (int nt = 0; nt < 8; nt++) {
        float e0 = __expf(s[mt][nt][0] * 0.125f) * rl[mt][0];
        float e1 = __expf(s[mt][nt][1] * 0.125f) * rl[mt][0];
        float e2 = __expf(s[mt][nt][2] * 0.125f) * rl[mt][1];
        float e3 = __expf(s[mt][nt][3] * 0.125f) * rl[mt][1];
        int cc = nt * 8 + 2 * tg;
        __stcs((float2*)&attn_b[(size_t)row0 * SS + kt * 64 + cc],
               make_float2(e0, e1));
        __stcs((float2*)&attn_b[(size_t)row1 * SS + kt * 64 + cc],
               make_float2(e2, e3));
      }
    }
  }
}

// ---------------------------------------------------------------------------
// Residual add + LayerNorm, one block per row.
// ---------------------------------------------------------------------------
__global__ __launch_bounds__(256) void add_ln_kernel(
    const float* __restrict__ fc, const float* __restrict__ res,
    const float* __restrict__ gamma, const float* __restrict__ beta,
    float* __restrict__ out) {
  int row = blockIdx.x;
  int tid = threadIdx.x;
  float4 xf = ((const float4*)(fc + (size_t)row * DM))[tid];
  float4 xr = ((const float4*)(res + (size_t)row * DM))[tid];
  float x0 = xf.x + xr.x, x1 = xf.y + xr.y, x2 = xf.z + xr.z, x3 = xf.w + xr.w;
  float s = x0 + x1 + x2 + x3;
  float sq = x0 * x0 + x1 * x1 + x2 * x2 + x3 * x3;
#pragma unroll
  for (int o = 16; o; o >>= 1) {
    s += __shfl_down_sync(0xffffffffu, s, o);
    sq += __shfl_down_sync(0xffffffffu, sq, o);
  }
  __shared__ float ws[8], wq[8];
  __shared__ float mu_s, rs_s;
  if ((tid & 31) == 0) { ws[tid >> 5] = s; wq[tid >> 5] = sq; }
  __syncthreads();
  if (tid == 0) {
    float St = 0.f, Qt = 0.f;
#pragma unroll
    for (int i = 0; i < 8; i++) { St += ws[i]; Qt += wq[i]; }
    float mu = St * (1.f / DM);
    float var = Qt * (1.f / DM) - mu * mu;
    mu_s = mu;
    rs_s = rsqrtf(var + 1e-6f);
  }
  __syncthreads();
  float mu = mu_s, rs = rs_s;
  float4 g = ((const float4*)gamma)[tid];
  float4 bb = ((const float4*)beta)[tid];
  float4 o;
  o.x = (x0 - mu) * rs * g.x + bb.x;
  o.y = (x1 - mu) * rs * g.y + bb.y;
  o.z = (x2 - mu) * rs * g.z + bb.z;
  o.w = (x3 - mu) * rs * g.w + bb.w;
  ((float4*)(out + (size_t)row * DM))[tid] = o;
}

// ---------------------------------------------------------------------------
extern "C" void kernel_launch(void* const* d_in, const int* in_sizes, int n_in,
                              void* d_out, int out_size) {
  const float* q = (const float*)d_in[0];
  const float* k = (const float*)d_in[1];
  const float* v = (const float*)d_in[2];
  const float* w_qs = (const float*)d_in[3];
  const float* w_ks = (const float*)d_in[4];
  const float* w_vs = (const float*)d_in[5];
  const float* w_fc = (const float*)d_in[6];
  const float* gamma = (const float*)d_in[7];
  const float* beta = (const float*)d_in[8];
  float* out = (float*)d_out;

  const size_t out_elems = (size_t)BB * SS * DM;                // 8388608
  const size_t attn_elems = (size_t)BB * NH * SS * (size_t)SS;  // 268435456
  float* attn = ((size_t)out_size >= out_elems + attn_elems)
                    ? out + out_elems
                    : nullptr;

  float *Pq, *Pk, *Pv, *ctxT, *fcb, *attn_fb;
  cudaGetSymbolAddress((void**)&Pq, g_Pq);
  cudaGetSymbolAddress((void**)&Pk, g_Pk);
  cudaGetSymbolAddress((void**)&Pv, g_Pv);
  cudaGetSymbolAddress((void**)&ctxT, g_ctxT);
  cudaGetSymbolAddress((void**)&fcb, g_fc);
  cudaGetSymbolAddress((void**)&attn_fb, g_attn_fallback);
  if (!attn) attn = attn_fb;

  cudaFuncSetAttribute(gemm_qkv, cudaFuncAttributeMaxDynamicSharedMemorySize,
                       GEMM_SMEM);
  cudaFuncSetAttribute(gemm_fc, cudaFuncAttributeMaxDynamicSharedMemorySize,
                       GEMM_SMEM);
  cudaFuncSetAttribute(attn_kernel,
                       cudaFuncAttributeMaxDynamicSharedMemorySize, ATTN_SMEM);

  gemm_qkv<<<dim3(DM / 128, (BB * SS) / 128, 3), 256, GEMM_SMEM>>>(
      q, k, v, w_qs, w_ks, w_vs, Pq, Pk, Pv);

  attn_kernel<<<dim3(SS / 128, BB * NH), 128, ATTN_SMEM>>>(Pq, Pk, Pv, attn,
                                                           ctxT);

  gemm_fc<<<dim3(DM / 128, (BB * SS) / 128), 256, GEMM_SMEM>>>(ctxT, w_fc,
                                                               fcb);
  add_ln_kernel<<<BB * SS, 256>>>(fcb, q, gamma, beta, out);
}

// round 14
// speedup vs baseline: 1.5362x; 1.5362x over previous
#include <cuda_runtime.h>
#include <cstdint>
#include <cstddef>

#define BB 4
#define SS 2048
#define DM 1024
#define NH 16
#define DK 64

// Scratch (allocation-free rule: __device__ globals)
__device__ float g_Pq[BB * SS * DM];
__device__ float g_Pk[BB * SS * DM];
__device__ float g_Pv[BB * SS * DM];
__device__ float g_ctxT[BB * SS * DM];
__device__ float g_fc[BB * SS * DM];
__device__ float g_attn_fallback[(size_t)BB * NH * SS * SS];

__device__ __forceinline__ uint32_t f2tf(float x) {
  uint32_t u;
  asm("cvt.rna.tf32.f32 %0, %1;" : "=r"(u) : "f"(x));
  return u;
}
__device__ __forceinline__ uint32_t su(const void* p) {
  return (uint32_t)__cvta_generic_to_shared(p);
}
__device__ __forceinline__ void cpa16(uint32_t s, const void* g) {
  asm volatile("cp.async.cg.shared.global [%0], [%1], 16;\n" ::"r"(s), "l"(g));
}
__device__ __forceinline__ void cpcommit() {
  asm volatile("cp.async.commit_group;\n");
}
template <int N>
__device__ __forceinline__ void cpwait() {
  asm volatile("cp.async.wait_group %0;\n" ::"n"(N));
}
__device__ __forceinline__ void ldsm4(uint32_t& r0, uint32_t& r1, uint32_t& r2,
                                      uint32_t& r3, uint32_t a) {
  asm volatile(
      "ldmatrix.sync.aligned.m8n8.x4.shared.b16 {%0,%1,%2,%3},[%4];\n"
      : "=r"(r0), "=r"(r1), "=r"(r2), "=r"(r3)
      : "r"(a));
}
__device__ __forceinline__ void mma_tf32(float* c, uint32_t a0, uint32_t a1,
                                         uint32_t a2, uint32_t a3, uint32_t b0,
                                         uint32_t b1) {
  asm volatile(
      "mma.sync.aligned.m16n8k8.row.col.f32.tf32.tf32.f32 "
      "{%0,%1,%2,%3},{%4,%5,%6,%7},{%8,%9},{%0,%1,%2,%3};\n"
      : "+f"(c[0]), "+f"(c[1]), "+f"(c[2]), "+f"(c[3])
      : "r"(a0), "r"(a1), "r"(a2), "r"(a3), "r"(b0), "r"(b1));
}

// ---------------------------------------------------------------------------
// tf32 GEMM core (NT): C[M,N] = A[M,K] * W[N,K]^T -- EXACT R5 body (proven
// ~90% of mma.sync floor; cvt-at-store, static smem, simple double-sync).
// Twice-confirmed: do not move cvt into the fragment-load path.
// RND rounds the output to tf32 for the QKV projections.
// ---------------------------------------------------------------------------
#define GST 36
template <bool RND>
__device__ __forceinline__ void gemm_core_r5(const float* __restrict__ A,
                                             const float* __restrict__ Bw,
                                             float* __restrict__ C, int M,
                                             int N, int K) {
  __shared__ uint32_t As[128 * GST];
  __shared__ uint32_t Bs[128 * GST];
  int tid = threadIdx.x, lane = tid & 31, wid = tid >> 5;
  int g = lane >> 2, tg = lane & 3;
  int m0 = (wid & 3) * 32, n0 = (wid >> 2) * 64;
  int bm = blockIdx.y * 128, bn = blockIdx.x * 128;

  float c[2][8][4];
#pragma unroll
  for (int mt = 0; mt < 2; mt++)
#pragma unroll
    for (int nt = 0; nt < 8; nt++)
#pragma unroll
      for (int j = 0; j < 4; j++) c[mt][nt][j] = 0.f;

  for (int k0 = 0; k0 < K; k0 += 32) {
    float4 av[4], bv[4];
#pragma unroll
    for (int i = 0; i < 4; i++) {
      int id = tid + i * 256;
      int m = id >> 3;
      int k4 = (id & 7) << 2;
      av[i] = *(const float4*)&A[(size_t)(bm + m) * K + k0 + k4];
      bv[i] = *(const float4*)&Bw[(size_t)(bn + m) * K + k0 + k4];
    }
    __syncthreads();
#pragma unroll
    for (int i = 0; i < 4; i++) {
      int id = tid + i * 256;
      int m = id >> 3;
      int k4 = (id & 7) << 2;
      *(uint4*)&As[m * GST + k4] =
          make_uint4(f2tf(av[i].x), f2tf(av[i].y), f2tf(av[i].z), f2tf(av[i].w));
      *(uint4*)&Bs[m * GST + k4] =
          make_uint4(f2tf(bv[i].x), f2tf(bv[i].y), f2tf(bv[i].z), f2tf(bv[i].w));
    }
    __syncthreads();
#pragma unroll
    for (int kk = 0; kk < 4; kk++) {
      int k = kk * 8;
      uint32_t a[2][4];
#pragma unroll
      for (int mt = 0; mt < 2; mt++) {
        int mm = m0 + mt * 16 + g;
        a[mt][0] = As[mm * GST + k + tg];
        a[mt][1] = As[(mm + 8) * GST + k + tg];
        a[mt][2] = As[mm * GST + k + tg + 4];
        a[mt][3] = As[(mm + 8) * GST + k + tg + 4];
      }
#pragma unroll
      for (int nt = 0; nt < 8; nt++) {
        int nn = n0 + nt * 8 + g;
        uint32_t b0 = Bs[nn * GST + k + tg];
        uint32_t b1 = Bs[nn * GST + k + tg + 4];
        mma_tf32(c[0][nt], a[0][0], a[0][1], a[0][2], a[0][3], b0, b1);
        mma_tf32(c[1][nt], a[1][0], a[1][1], a[1][2], a[1][3], b0, b1);
      }
    }
  }

#pragma unroll
  for (int mt = 0; mt < 2; mt++)
#pragma unroll
    for (int nt = 0; nt < 8; nt++) {
      int row0 = bm + m0 + mt * 16 + g;
      int col = bn + n0 + nt * 8 + 2 * tg;
      float v0 = c[mt][nt][0], v1 = c[mt][nt][1];
      float v2 = c[mt][nt][2], v3 = c[mt][nt][3];
      if (RND) {
        v0 = __uint_as_float(f2tf(v0));
        v1 = __uint_as_float(f2tf(v1));
        v2 = __uint_as_float(f2tf(v2));
        v3 = __uint_as_float(f2tf(v3));
      }
      *(float2*)&C[(size_t)row0 * N + col] = make_float2(v0, v1);
      *(float2*)&C[(size_t)(row0 + 8) * N + col] = make_float2(v2, v3);
    }
}

// Fused QKV projections: gridDim.z selects (input, weight, output).
// One 192-block wave instead of three half-empty 64-block waves.
__global__ __launch_bounds__(256) void gemm_qkv(
    const float* __restrict__ q, const float* __restrict__ k,
    const float* __restrict__ v, const float* __restrict__ wq,
    const float* __restrict__ wk, const float* __restrict__ wv,
    float* __restrict__ Pq, float* __restrict__ Pk, float* __restrict__ Pv) {
  const float* A = (blockIdx.z == 0) ? q : (blockIdx.z == 1) ? k : v;
  const float* W = (blockIdx.z == 0) ? wq : (blockIdx.z == 1) ? wk : wv;
  float* C = (blockIdx.z == 0) ? Pq : (blockIdx.z == 1) ? Pk : Pv;
  gemm_core_r5<true>(A, W, C, BB * SS, DM, DM);
}

__global__ __launch_bounds__(256) void gemm_fc(const float* __restrict__ A,
                                               const float* __restrict__ W,
                                               float* __restrict__ C) {
  gemm_core_r5<false>(A, W, C, BB * SS, DM, DM);
}

// ---------------------------------------------------------------------------
// Attention, two-pass normalization, 32-row warp tiles (proven R11 kernel,
// byte-for-byte).
// ---------------------------------------------------------------------------
#define AST 68
#define VST 72
#define QS_W 0
#define KS_W 8704
#define KS_STG 4352
#define VS_W 17408
#define VS_STG 4608
#define ATTN_SMEM (26624 * 4)

__global__ __launch_bounds__(128, 2) void attn_kernel(
    const float* __restrict__ Pq, const float* __restrict__ Pk,
    const float* __restrict__ Pv, float* __restrict__ attn,
    float* __restrict__ ctxT) {
  extern __shared__ float smf[];

  int tid = threadIdx.x, lane = tid & 31, wid = tid >> 5;
  int sub = lane >> 3, l7 = lane & 7;
  int g = lane >> 2, tg = lane & 3;
  int m0 = wid * 32;    // warp's 32 Q-rows (block-local)
  int qt = blockIdx.x;  // 0..15 (128-row Q tiles)
  int bh = blockIdx.y;
  int b = bh >> 4, h = bh & 15;

  const float* Qb = Pq + (size_t)b * SS * DM + (size_t)h * SS * DK;
  const float* Kb = Pk + (size_t)b * SS * DM + (size_t)h * SS * DK;
  const float* Vb = Pv + (size_t)b * SS * DM + (size_t)h * SS * DK;
  float* attn_b = attn + ((size_t)bh * SS + (size_t)qt * 128) * SS;

  uint32_t sbase = su(smf);

  uint32_t qOff0 =
      sbase + (QS_W + (m0 + (sub & 1) * 8 + l7) * AST + (sub >> 1) * 4) * 4;
  uint32_t qOff1 = qOff0 + 16 * AST * 4;
  uint32_t kLane = (((sub >> 1) * 8 + l7) * AST + (sub & 1) * 4) * 4;

  int qrow[16], qcol[16];
#pragma unroll
  for (int i = 0; i < 16; i++) {
    int cc = tid + i * 128;
    qrow[i] = cc >> 4;
    qcol[i] = (cc & 15) << 2;
  }
  int crow[8], ccol[8];
#pragma unroll
  for (int i = 0; i < 8; i++) {
    int cc = tid + i * 128;
    crow[i] = cc >> 4;
    ccol[i] = (cc & 15) << 2;
  }

  // prologue: Q + K0 + V0 (one group)
#pragma unroll
  for (int i = 0; i < 16; i++)
    cpa16(sbase + (QS_W + qrow[i] * AST + qcol[i]) * 4,
          Qb + (size_t)(qt * 128 + qrow[i]) * DK + qcol[i]);
#pragma unroll
  for (int i = 0; i < 8; i++) {
    cpa16(sbase + (KS_W + crow[i] * AST + ccol[i]) * 4,
          Kb + (size_t)crow[i] * DK + ccol[i]);
    cpa16(sbase + (VS_W + crow[i] * VST + ccol[i]) * 4,
          Vb + (size_t)crow[i] * DK + ccol[i]);
  }
  cpcommit();

  float o[2][8][4];
#pragma unroll
  for (int mt = 0; mt < 2; mt++)
#pragma unroll
    for (int nt = 0; nt < 8; nt++)
#pragma unroll
      for (int j = 0; j < 4; j++) o[mt][nt][j] = 0.f;
  float racc[2][2] = {{0.f, 0.f}, {0.f, 0.f}};

  const int NT = SS / 64;

  // ================= Pass A: rowsums + PV (no attn write) =================
  for (int kt = 0; kt < NT; kt++) {
    int st = kt & 1;
    cpwait<0>();
    __syncthreads();

    if (kt + 1 < NT) {
#pragma unroll
      for (int i = 0; i < 8; i++) {
        cpa16(sbase + (KS_W + (st ^ 1) * KS_STG + crow[i] * AST + ccol[i]) * 4,
              Kb + (size_t)((kt + 1) * 64 + crow[i]) * DK + ccol[i]);
        cpa16(sbase + (VS_W + (st ^ 1) * VS_STG + crow[i] * VST + ccol[i]) * 4,
              Vb + (size_t)((kt + 1) * 64 + crow[i]) * DK + ccol[i]);
      }
      cpcommit();
    }

    float s[2][8][4];
#pragma unroll
    for (int mt = 0; mt < 2; mt++)
#pragma unroll
      for (int nt = 0; nt < 8; nt++)
#pragma unroll
        for (int j = 0; j < 4; j++) s[mt][nt][j] = 0.f;
    uint32_t kBase = sbase + (KS_W + st * KS_STG) * 4 + kLane;
#pragma unroll
    for (int kk = 0; kk < 8; kk++) {
      uint32_t qa0[4], qa1[4];
      ldsm4(qa0[0], qa0[1], qa0[2], qa0[3], qOff0 + kk * 32);
      ldsm4(qa1[0], qa1[1], qa1[2], qa1[3], qOff1 + kk * 32);
#pragma unroll
      for (int p = 0; p < 4; p++) {
        uint32_t kb[4];
        ldsm4(kb[0], kb[1], kb[2], kb[3], kBase + p * 16 * AST * 4 + kk * 32);
        mma_tf32(s[0][2 * p], qa0[0], qa0[1], qa0[2], qa0[3], kb[0], kb[1]);
        mma_tf32(s[0][2 * p + 1], qa0[0], qa0[1], qa0[2], qa0[3], kb[2], kb[3]);
        mma_tf32(s[1][2 * p], qa1[0], qa1[1], qa1[2], qa1[3], kb[0], kb[1]);
        mma_tf32(s[1][2 * p + 1], qa1[0], qa1[1], qa1[2], qa1[3], kb[2], kb[3]);
      }
    }

    // fused exp + PV per k-step kk
    int vsBase = VS_W + st * VS_STG;
#pragma unroll
    for (int kk = 0; kk < 8; kk++) {
      uint32_t a[2][4];
#pragma unroll
      for (int mt = 0; mt < 2; mt++) {
        float e0 = __expf(s[mt][kk][0] * 0.125f);
        float e1 = __expf(s[mt][kk][1] * 0.125f);
        float e2 = __expf(s[mt][kk][2] * 0.125f);
        float e3 = __expf(s[mt][kk][3] * 0.125f);
        racc[mt][0] += e0 + e1;
        racc[mt][1] += e2 + e3;
        uint32_t t0 = f2tf(e0), t1 = f2tf(e1), t2 = f2tf(e2), t3 = f2tf(e3);
        int qlo = tg >> 1, qhi = (tg >> 1) + 2;
        uint32_t lo0 = __shfl_sync(0xffffffffu, t0, qlo, 4);
        uint32_t lo1 = __shfl_sync(0xffffffffu, t1, qlo, 4);
        uint32_t lo2 = __shfl_sync(0xffffffffu, t2, qlo, 4);
        uint32_t lo3 = __shfl_sync(0xffffffffu, t3, qlo, 4);
        uint32_t hi0 = __shfl_sync(0xffffffffu, t0, qhi, 4);
        uint32_t hi1 = __shfl_sync(0xffffffffu, t1, qhi, 4);
        uint32_t hi2 = __shfl_sync(0xffffffffu, t2, qhi, 4);
        uint32_t hi3 = __shfl_sync(0xffffffffu, t3, qhi, 4);
        a[mt][0] = (tg & 1) ? lo1 : lo0;
        a[mt][1] = (tg & 1) ? lo3 : lo2;
        a[mt][2] = (tg & 1) ? hi1 : hi0;
        a[mt][3] = (tg & 1) ? hi3 : hi2;
      }
      int kr0 = vsBase + (kk * 8 + tg) * VST;
      int kr1 = vsBase + (kk * 8 + tg + 4) * VST;
#pragma unroll
      for (int nt = 0; nt < 8; nt++) {
        uint32_t b0 = __float_as_uint(smf[kr0 + nt * 8 + g]);
        uint32_t b1 = __float_as_uint(smf[kr1 + nt * 8 + g]);
        mma_tf32(o[0][nt], a[0][0], a[0][1], a[0][2], a[0][3], b0, b1);
        mma_tf32(o[1][nt], a[1][0], a[1][1], a[1][2], a[1][3], b0, b1);
      }
    }
  }

  // quad-reduce rowsums
  float rl[2][2];
#pragma unroll
  for (int mt = 0; mt < 2; mt++)
#pragma unroll
    for (int i = 0; i < 2; i++) {
      float r = racc[mt][i];
      r += __shfl_xor_sync(0xffffffffu, r, 1);
      r += __shfl_xor_sync(0xffffffffu, r, 2);
      rl[mt][i] = 1.f / r;
    }

  // normalize ctx, write [b, s, h*64 + d]
#pragma unroll
  for (int mt = 0; mt < 2; mt++) {
    int row0 = qt * 128 + m0 + mt * 16 + g, row1 = row0 + 8;
#pragma unroll
    for (int nt = 0; nt < 8; nt++) {
      int col = h * DK + nt * 8 + 2 * tg;
      *(float2*)&g_ctxT[(size_t)b * SS * DM + (size_t)row0 * DM + col] =
          make_float2(o[mt][nt][0] * rl[mt][0], o[mt][nt][1] * rl[mt][0]);
      *(float2*)&g_ctxT[(size_t)b * SS * DM + (size_t)row1 * DM + col] =
          make_float2(o[mt][nt][2] * rl[mt][1], o[mt][nt][3] * rl[mt][1]);
    }
  }
  (void)ctxT;

  // ======= Pass B: recompute S bitwise-identically, write normalized =======
#pragma unroll
  for (int i = 0; i < 8; i++)
    cpa16(sbase + (KS_W + crow[i] * AST + ccol[i]) * 4,
          Kb + (size_t)crow[i] * DK + ccol[i]);
  cpcommit();

  for (int kt = 0; kt < NT; kt++) {
    int st = kt & 1;
    cpwait<0>();
    __syncthreads();

    if (kt + 1 < NT) {
#pragma unroll
      for (int i = 0; i < 8; i++)
        cpa16(sbase + (KS_W + (st ^ 1) * KS_STG + crow[i] * AST + ccol[i]) * 4,
              Kb + (size_t)((kt + 1) * 64 + crow[i]) * DK + ccol[i]);
      cpcommit();
    }

    float s[2][8][4];
#pragma unroll
    for (int mt = 0; mt < 2; mt++)
#pragma unroll
      for (int nt = 0; nt < 8; nt++)
#pragma unroll
        for (int j = 0; j < 4; j++) s[mt][nt][j] = 0.f;
    uint32_t kBase = sbase + (KS_W + st * KS_STG) * 4 + kLane;
#pragma unroll
    for (int kk = 0; kk < 8; kk++) {
      uint32_t qa0[4], qa1[4];
      ldsm4(qa0[0], qa0[1], qa0[2], qa0[3], qOff0 + kk * 32);
      ldsm4(qa1[0], qa1[1], qa1[2], qa1[3], qOff1 + kk * 32);
#pragma unroll
      for (int p = 0; p < 4; p++) {
        uint32_t kb[4];
        ldsm4(kb[0], kb[1], kb[2], kb[3], kBase + p * 16 * AST * 4 + kk * 32);
        mma_tf32(s[0][2 * p], qa0[0], qa0[1], qa0[2], qa0[3], kb[0], kb[1]);
        mma_tf32(s[0][2 * p + 1], qa0[0], qa0[1], qa0[2], qa0[3], kb[2], kb[3]);
        mma_tf32(s[1][2 * p], qa1[0], qa1[1], qa1[2], qa1[3], kb[0], kb[1]);
        mma_tf32(s[1][2 * p + 1], qa1[0], qa1[1], qa1[2], qa1[3], kb[2], kb[3]);
      }
    }

#pragma unroll
    for (int mt = 0; mt < 2; mt++) {
      int row0 = m0 + mt * 16 + g, row1 = row0 + 8;
#pragma unroll
      for (int nt = 0; nt < 8; nt++) {
        float e0 = __expf(s[mt][nt][0] * 0.125f) * rl[mt][0];
        float e1 = __expf(s[mt][nt][1] * 0.125f) * rl[mt][0];
        float e2 = __expf(s[mt][nt][2] * 0.125f) * rl[mt][1];
        float e3 = __expf(s[mt][nt][3] * 0.125f) * rl[mt][1];
        int cc = nt * 8 + 2 * tg;
        __stcs((float2*)&attn_b[(size_t)row0 * SS + kt * 64 + cc],
               make_float2(e0, e1));
        __stcs((float2*)&attn_b[(size_t)row1 * SS + kt * 64 + cc],
               make_float2(e2, e3));
      }
    }
  }
}

// ---------------------------------------------------------------------------
// Residual add + LayerNorm, one block per row.
// ---------------------------------------------------------------------------
__global__ __launch_bounds__(256) void add_ln_kernel(
    const float* __restrict__ fc, const float* __restrict__ res,
    const float* __restrict__ gamma, const float* __restrict__ beta,
    float* __restrict__ out) {
  int row = blockIdx.x;
  int tid = threadIdx.x;
  float4 xf = ((const float4*)(fc + (size_t)row * DM))[tid];
  float4 xr = ((const float4*)(res + (size_t)row * DM))[tid];
  float x0 = xf.x + xr.x, x1 = xf.y + xr.y, x2 = xf.z + xr.z, x3 = xf.w + xr.w;
  float s = x0 + x1 + x2 + x3;
  float sq = x0 * x0 + x1 * x1 + x2 * x2 + x3 * x3;
#pragma unroll
  for (int o = 16; o; o >>= 1) {
    s += __shfl_down_sync(0xffffffffu, s, o);
    sq += __shfl_down_sync(0xffffffffu, sq, o);
  }
  __shared__ float ws[8], wq[8];
  __shared__ float mu_s, rs_s;
  if ((tid & 31) == 0) { ws[tid >> 5] = s; wq[tid >> 5] = sq; }
  __syncthreads();
  if (tid == 0) {
    float St = 0.f, Qt = 0.f;
#pragma unroll
    for (int i = 0; i < 8; i++) { St += ws[i]; Qt += wq[i]; }
    float mu = St * (1.f / DM);
    float var = Qt * (1.f / DM) - mu * mu;
    mu_s = mu;
    rs_s = rsqrtf(var + 1e-6f);
  }
  __syncthreads();
  float mu = mu_s, rs = rs_s;
  float4 g = ((const float4*)gamma)[tid];
  float4 bb = ((const float4*)beta)[tid];
  float4 o;
  o.x = (x0 - mu) * rs * g.x + bb.x;
  o.y = (x1 - mu) * rs * g.y + bb.y;
  o.z = (x2 - mu) * rs * g.z + bb.z;
  o.w = (x3 - mu) * rs * g.w + bb.w;
  ((float4*)(out + (size_t)row * DM))[tid] = o;
}

// ---------------------------------------------------------------------------
extern "C" void kernel_launch(void* const* d_in, const int* in_sizes, int n_in,
                              void* d_out, int out_size) {
  const float* q = (const float*)d_in[0];
  const float* k = (const float*)d_in[1];
  const float* v = (const float*)d_in[2];
  const float* w_qs = (const float*)d_in[3];
  const float* w_ks = (const float*)d_in[4];
  const float* w_vs = (const float*)d_in[5];
  const float* w_fc = (const float*)d_in[6];
  const float* gamma = (const float*)d_in[7];
  const float* beta = (const float*)d_in[8];
  float* out = (float*)d_out;

  const size_t out_elems = (size_t)BB * SS * DM;                // 8388608
  const size_t attn_elems = (size_t)BB * NH * SS * (size_t)SS;  // 268435456
  float* attn = ((size_t)out_size >= out_elems + attn_elems)
                    ? out + out_elems
                    : nullptr;

  float *Pq, *Pk, *Pv, *ctxT, *fcb, *attn_fb;
  cudaGetSymbolAddress((void**)&Pq, g_Pq);
  cudaGetSymbolAddress((void**)&Pk, g_Pk);
  cudaGetSymbolAddress((void**)&Pv, g_Pv);
  cudaGetSymbolAddress((void**)&ctxT, g_ctxT);
  cudaGetSymbolAddress((void**)&fcb, g_fc);
  cudaGetSymbolAddress((void**)&attn_fb, g_attn_fallback);
  if (!attn) attn = attn_fb;

  cudaFuncSetAttribute(attn_kernel,
                       cudaFuncAttributeMaxDynamicSharedMemorySize, ATTN_SMEM);

  gemm_qkv<<<dim3(DM / 128, (BB * SS) / 128, 3), 256>>>(q, k, v, w_qs, w_ks,
                                                        w_vs, Pq, Pk, Pv);

  attn_kernel<<<dim3(SS / 128, BB * NH), 128, ATTN_SMEM>>>(Pq, Pk, Pv, attn,
                                                           ctxT);

  gemm_fc<<<dim3(DM / 128, (BB * SS) / 128), 256>>>(ctxT, w_fc, fcb);
  add_ln_kernel<<<BB * SS, 256>>>(fcb, q, gamma, beta, out);
}